// round 17
// baseline (speedup 1.0000x reference)
#include <cuda_runtime.h>
#include <math.h>

#define EPS_V    1e-6f
#define MARGIN_V 1.0f

// Scratch (allocation-free rule: __device__ globals)
__device__ float        g_dap[64];
__device__ float        g_dan[50048];     // per-row d_an (200KB, L2-resident)
__device__ float        g_partials[64];
__device__ unsigned int g_count = 0;      // reset by last block each launch

// ---------------------------------------------------------------------------
// K1: blocks 0..P-1 compute d_ap[p] (overlapped, wave 1); blocks P.. stream
// one negative row per warp (unchanged 7.0 TB/s hot path).
// ---------------------------------------------------------------------------
__global__ void __launch_bounds__(256) dan_kernel(
        const float* __restrict__ anchor,
        const float* __restrict__ pos,
        const float* __restrict__ neg,
        int D, int R, int P) {
    extern __shared__ float4 s_a4[];           // D/4 float4 of anchor
    __shared__ float s_red[8];

    const int D4   = D >> 2;
    const int lane = threadIdx.x & 31;
    const int wid  = threadIdx.x >> 5;

    // stage anchor into smem (vectorized) — both paths use it
    const float4* __restrict__ a4 = (const float4*)anchor;
    for (int i = threadIdx.x; i < D4; i += blockDim.x) s_a4[i] = a4[i];
    __syncthreads();

    if (blockIdx.x < (unsigned)P) {
        // --- cold path: whole block computes d_ap[blockIdx] ---
        const int p = blockIdx.x;
        const float4* __restrict__ x4 = (const float4*)(pos + (size_t)p * D);
        float ss = 0.0f;
        for (int i = threadIdx.x; i < D4; i += blockDim.x) {
            float4 x = x4[i];
            float4 a = s_a4[i];
            float d0 = a.x - x.x + EPS_V;
            float d1 = a.y - x.y + EPS_V;
            float d2 = a.z - x.z + EPS_V;
            float d3 = a.w - x.w + EPS_V;
            ss = fmaf(d0, d0, ss);
            ss = fmaf(d1, d1, ss);
            ss = fmaf(d2, d2, ss);
            ss = fmaf(d3, d3, ss);
        }
        #pragma unroll
        for (int off = 16; off > 0; off >>= 1)
            ss += __shfl_xor_sync(0xffffffffu, ss, off);
        if (lane == 0) s_red[wid] = ss;
        __syncthreads();
        if (threadIdx.x == 0) {
            float tot = 0.0f;
            #pragma unroll
            for (int w = 0; w < 8; ++w) tot += s_red[w];
            g_dap[p] = sqrtf(tot);
        }
        return;
    }

    // --- hot path: one warp per negative row (unchanged) ---
    const int row = (blockIdx.x - P) * 8 + wid;
    if (row >= R) return;

    const float4* __restrict__ x4 = (const float4*)(neg + (size_t)row * D);
    float ss = 0.0f;
    #pragma unroll 4
    for (int i = lane; i < D4; i += 32) {
        float4 x = x4[i];
        float4 a = s_a4[i];
        float d0 = a.x - x.x + EPS_V;
        float d1 = a.y - x.y + EPS_V;
        float d2 = a.z - x.z + EPS_V;
        float d3 = a.w - x.w + EPS_V;
        ss = fmaf(d0, d0, ss);
        ss = fmaf(d1, d1, ss);
        ss = fmaf(d2, d2, ss);
        ss = fmaf(d3, d3, ss);
    }
    #pragma unroll
    for (int off = 16; off > 0; off >>= 1)
        ss += __shfl_xor_sync(0xffffffffu, ss, off);
    if (lane == 0) g_dan[row] = sqrtf(ss);
}

// ---------------------------------------------------------------------------
// K2: latency-optimal epilogue. One float4 of g_dan per thread (single L2
// round trip), r%P computed once per thread then incremented. Last-arriving
// block does the fixed-order final sum and resets the counter.
// ---------------------------------------------------------------------------
__global__ void __launch_bounds__(256) finish_kernel(
        float* __restrict__ out,
        int R, int P, int nBlocks) {
    __shared__ float s_dap[8];
    __shared__ float s_red[8];
    __shared__ bool  s_last;

    const int lane = threadIdx.x & 31;
    const int wid  = threadIdx.x >> 5;

    if (threadIdx.x < (unsigned)P) s_dap[threadIdx.x] = g_dap[threadIdx.x];
    __syncthreads();

    const int r0 = (blockIdx.x * blockDim.x + threadIdx.x) * 4;
    float acc = 0.0f;
    if (r0 < R) {
        float4 v = *(const float4*)&g_dan[r0];     // single L2-hit load
        int m = r0 % P;                            // one division per thread
        acc += fmaxf(s_dap[m] - v.x + MARGIN_V, 0.0f);
        m = (m + 1 == P) ? 0 : m + 1;
        if (r0 + 1 < R) acc += fmaxf(s_dap[m] - v.y + MARGIN_V, 0.0f);
        m = (m + 1 == P) ? 0 : m + 1;
        if (r0 + 2 < R) acc += fmaxf(s_dap[m] - v.z + MARGIN_V, 0.0f);
        m = (m + 1 == P) ? 0 : m + 1;
        if (r0 + 3 < R) acc += fmaxf(s_dap[m] - v.w + MARGIN_V, 0.0f);
    }

    #pragma unroll
    for (int off = 16; off > 0; off >>= 1)
        acc += __shfl_xor_sync(0xffffffffu, acc, off);
    if (lane == 0) s_red[wid] = acc;
    __syncthreads();

    if (threadIdx.x == 0) {
        float tot = 0.0f;
        #pragma unroll
        for (int w = 0; w < 8; ++w) tot += s_red[w];
        g_partials[blockIdx.x] = tot;
        __threadfence();
        unsigned int old = atomicAdd(&g_count, 1u);
        s_last = (old == (unsigned)(nBlocks - 1));
    }
    __syncthreads();

    if (s_last && threadIdx.x == 0) {
        __threadfence();
        float tot = 0.0f;
        for (int b = 0; b < nBlocks; ++b) tot += g_partials[b];
        out[0] = tot;
        g_count = 0;                       // reset for next graph replay
    }
}

// ---------------------------------------------------------------------------
extern "C" void kernel_launch(void* const* d_in, const int* in_sizes, int n_in,
                              void* d_out, int out_size) {
    const float* anchor = (const float*)d_in[0];
    const float* pos    = (const float*)d_in[1];
    const float* neg    = (const float*)d_in[2];
    float* out          = (float*)d_out;

    const int D = in_sizes[0];            // 2400
    const int P = in_sizes[1] / D;        // 5
    const int N = in_sizes[2] / D;        // 50000
    const int C = N / P;                  // 10000
    const int R = C * P;                  // 50000 rows used

    const int nBlocks = P + (R + 7) / 8;  // 5 dap blocks + 6250 streaming blocks
    const size_t smem = (size_t)(D >> 2) * sizeof(float4);
    dan_kernel<<<nBlocks, 256, smem>>>(anchor, pos, neg, D, R, P);

    const int fBlocks = (R + 1023) / 1024;  // 49: one float4 per thread
    finish_kernel<<<fBlocks, 256>>>(out, R, P, fBlocks);
}